// round 10
// baseline (speedup 1.0000x reference)
#include <cuda_runtime.h>

#define TT 300

// ---------------- static scratch (no allocations allowed) ----------------
__device__ float g_a [78643200];   // conv outputs (max: layer1, 16*16*32*32*300)
__device__ float g_sA[78643200];   // ping buffer
__device__ float g_sB[19660800];   // pong buffer
__device__ float g_u [48000];      // dense pre-psp output (combined)
__device__ float g_up[192000];     // dense split-K partials (4 x 48000)

// ---------------- double-float constant splits (compile-time folded) ------
constexpr double DDd   = 0.9048374180359595;     // exp(-0.1)
constexpr double D2d   = 0.8187307530779818;     // exp(-0.2)
constexpr double TD2d  = 1.6374615061559637;     // 2*exp(-0.2)
constexpr double CC1d  = 0.2718281828459045;     // e/10
constexpr double CC1Dd = CC1d * DDd;             // (e/10)*exp(-0.1)
constexpr double CC2d  = 1.2340980408667956e-3;  // 10*exp(-9)
constexpr double CC3d  = 1.2340980408667956e-5;  // 0.1*exp(-9)
constexpr float DD_H   = (float)DDd;
constexpr float DD_L   = (float)(DDd   - (double)DD_H);
constexpr float D2_H   = (float)D2d;
constexpr float D2_L   = (float)(D2d   - (double)D2_H);
constexpr float TD2_H  = (float)TD2d;
constexpr float TD2_L  = (float)(TD2d  - (double)TD2_H);
constexpr float CC1_H  = (float)CC1d;
constexpr float CC1_L  = (float)(CC1d  - (double)CC1_H);
constexpr float CC1D_H = (float)CC1Dd;
constexpr float CC1D_L = (float)(CC1Dd - (double)CC1D_H);
constexpr float CC2_H  = (float)CC2d;
constexpr float CC2_L  = (float)(CC2d  - (double)CC2_H);
constexpr float CC3_H  = (float)CC3d;

// ---------------- double-float (two-float) primitives ---------------------
struct df { float h, l; };

__device__ __forceinline__ df df_add(df a, df b) {
    float s  = a.h + b.h;
    float bb = s - a.h;
    float e  = (a.h - (s - bb)) + (b.h - bb);
    e += a.l + b.l;
    float h = s + e;
    float l = e - (h - s);
    return {h, l};
}
__device__ __forceinline__ df df_addf(df a, float b) {
    float s  = a.h + b;
    float bb = s - a.h;
    float e  = (a.h - (s - bb)) + (b - bb);
    e += a.l;
    float h = s + e;
    float l = e - (h - s);
    return {h, l};
}
__device__ __forceinline__ df df_mulc(df a, float ch, float cl) {
    float p = a.h * ch;
    float e = fmaf(a.h, ch, -p);
    e = fmaf(a.h, cl, e);
    e = fmaf(a.l, ch, e);
    float h = p + e;
    float l = e - (h - p);
    return {h, l};
}

// =====================================================================
// Spatial conv with LANE-SPLIT accumulators: 8 lanes (ci mod NL), direct
// fp32 FMA chains (<=36 terms, ~1.5e-6 err/lane), exact Neumaier tree at
// the end only (combine overhead ~0.5% of flops vs 40% for per-ci TwoSum).
// threads = t (coalesced). z = b + 16*co_group.
// =====================================================================
template<int CI,int NL,int CO_T,int CO_FULL,int KH,int KW,int HIN,int WIN,int HOUT,int WOUT,int PAD>
__global__ void __launch_bounds__(320)
conv_kernel(const float* __restrict__ in, const float* __restrict__ w,
            float* __restrict__ out)
{
    __shared__ __align__(16) float sw[CI*KH*KW*CO_T];
    const int tid = threadIdx.x;
    const int ow = blockIdx.x, oh = blockIdx.y;
    const int b = blockIdx.z & 15;
    const int co_base = (blockIdx.z >> 4) * CO_T;

    for (int i = tid; i < CI*KH*KW*CO_T; i += 320) {
        int k = i / CO_T, co = i % CO_T;
        sw[i] = w[(co_base + co)*(CI*KH*KW) + k];
    }
    __syncthreads();

    const int t = tid;
    if (t >= TT) return;

    float acc[NL][CO_T];
#pragma unroll
    for (int l = 0; l < NL; l++)
#pragma unroll
        for (int c = 0; c < CO_T; c++) acc[l][c] = 0.f;

    for (int g = 0; g < CI/NL; g++) {
#pragma unroll
        for (int l = 0; l < NL; l++) {
            const int ci = g*NL + l;
#pragma unroll
            for (int kh = 0; kh < KH; kh++) {
                const int ih = oh + kh - PAD;
#pragma unroll
                for (int kw = 0; kw < KW; kw++) {
                    const int iw = ow + kw - PAD;
                    const bool valid = ((unsigned)ih < (unsigned)HIN) && ((unsigned)iw < (unsigned)WIN);
                    const float* p = in + ((((b*CI + ci)*HIN + ih)*WIN) + iw)*TT;
                    const float x = valid ? p[t] : 0.f;
                    const float4* wv = reinterpret_cast<const float4*>(&sw[((ci*KH + kh)*KW + kw)*CO_T]);
#pragma unroll
                    for (int c4 = 0; c4 < CO_T/4; c4++) {
                        float4 wq = wv[c4];
                        acc[l][c4*4+0] = fmaf(wq.x, x, acc[l][c4*4+0]);
                        acc[l][c4*4+1] = fmaf(wq.y, x, acc[l][c4*4+1]);
                        acc[l][c4*4+2] = fmaf(wq.z, x, acc[l][c4*4+2]);
                        acc[l][c4*4+3] = fmaf(wq.w, x, acc[l][c4*4+3]);
                    }
                }
            }
        }
    }

    // exact Neumaier combine across lanes (once per output)
#pragma unroll
    for (int c = 0; c < CO_T; c++) {
        float s_  = acc[0][c];
        float cmp = 0.f;
#pragma unroll
        for (int l = 1; l < NL; l++) {
            float bv = acc[l][c];
            float tv = s_ + bv;
            float bb = tv - s_;
            cmp += (s_ - (tv - bb)) + (bv - bb);
            s_ = tv;
        }
        float* q = out + ((((b*CO_FULL) + (co_base + c))*HOUT + oh)*WOUT + ow)*TT;
        q[t] = s_ + cmp;
    }
}

// =====================================================================
// PSP (2-step-blocked double-float IIR + fp32 delayed-tail IIR) fused with
// the bit-exact refractory scan, and (POOLW>0) the SLAYER 2x2 sum-pool
// (11 * sum of 4 binary spikes — exact in fp32, any order).
// POOLW = spatial row width (32 or 16); POOLW=0 -> plain spike output.
// 128 neurons/block; 32-t tiles; float4 staged I/O; next-tile prefetch.
// =====================================================================
template<int POOLW>
__global__ void __launch_bounds__(128)
psp_spike_kernel(const float* __restrict__ a, float* __restrict__ s, int N)
{
    __shared__ __align__(16) float sx[128][36];   // current tile (spikes in-place)
    __shared__ __align__(16) float sd[128][36];   // 100-delayed tile
    const int tid = threadIdx.x;
    const int n0 = blockIdx.x * 128;
    const int n  = n0 + tid;

    df Z = {0.f, 0.f}, P = {0.f, 0.f};
    float Z2t = 0.f, P2t = 0.f;
    float r   = 0.f;

    float4 curv[8], delv[8];

    // ---- prefetch tile 0 ----
#pragma unroll
    for (int q = 0; q < 8; q++) {
        const int flat = q*128 + tid;
        const int row = flat >> 3, c4 = flat & 7;
        const int nn = n0 + row;
        const int t = c4*4;
        float4 v = {0.f,0.f,0.f,0.f}, wv = {0.f,0.f,0.f,0.f};
        if (nn < N && t < TT)
            v = *reinterpret_cast<const float4*>(a + (size_t)nn*TT + t);
        curv[q] = v; delv[q] = wv;
    }

    for (int t0 = 0; t0 < TT; t0 += 32) {
#pragma unroll
        for (int q = 0; q < 8; q++) {
            const int flat = q*128 + tid;
            const int row = flat >> 3, c4 = flat & 7;
            *reinterpret_cast<float4*>(&sx[row][c4*4]) = curv[q];
            *reinterpret_cast<float4*>(&sd[row][c4*4]) = delv[q];
        }
        __syncthreads();

        const int t0n = t0 + 32;
        if (t0n < TT) {
#pragma unroll
            for (int q = 0; q < 8; q++) {
                const int flat = q*128 + tid;
                const int row = flat >> 3, c4 = flat & 7;
                const int nn = n0 + row;
                const int t = t0n + c4*4;
                float4 v = {0.f,0.f,0.f,0.f}, wv = {0.f,0.f,0.f,0.f};
                if (nn < N) {
                    if (t < TT)
                        v = *reinterpret_cast<const float4*>(a + (size_t)nn*TT + t);
                    const int td = t - 100;
                    if (td >= 0 && td < TT)
                        wv = *reinterpret_cast<const float4*>(a + (size_t)nn*TT + td);
                }
                curv[q] = v; delv[q] = wv;
            }
        }

        if (n < N) {
            const int tmax = min(32, TT - t0);    // 32 or 12, both /4
            for (int tq = 0; tq < tmax; tq += 4) {
                float4 X  = *reinterpret_cast<const float4*>(&sx[tid][tq]);
                float4 XD = *reinterpret_cast<const float4*>(&sd[tid][tq]);
                float sp[4];
#pragma unroll
                for (int h = 0; h < 2; h++) {
                    const float x0  = (h == 0) ? X.x  : X.z;
                    const float x1  = (h == 0) ? X.y  : X.w;
                    const float xd0 = (h == 0) ? XD.x : XD.z;
                    const float xd1 = (h == 0) ? XD.y : XD.w;

                    // dx0 = d (x) x0, exact product
                    float ph = DD_H * x0;
                    float pl = fmaf(DD_H, x0, -ph);
                    pl = fmaf(DD_L, x0, pl);
                    // Z_{t+2} = d^2 Z + 2 d^2 P + dx0
                    df A = df_mulc(Z, D2_H, D2_L);
                    df B = df_mulc(P, TD2_H, TD2_L);
                    df Znew = df_add(df_add(A, B), df{ph, pl});
                    // P_{t+2} = d^2 P + dx0 + x1
                    df Cv = df_mulc(P, D2_H, D2_L);
                    df Pnew = df_addf(df_add(Cv, df{ph, pl}), x1);

                    // tail step 0 + y0 (y0 = CC1*d*(Z+P) - tail0) + spike
                    Z2t = DD_H * (Z2t + P2t);
                    P2t = fmaf(DD_H, P2t, xd0);
                    float tail0 = fmaf(CC2_H, P2t, fmaf(CC3_H, Z2t, CC2_L * P2t));
                    float sh = (Z.h + P.h) + (Z.l + P.l);
                    float y0 = fmaf(CC1D_H, sh, fmaf(CC1D_L, sh, -tail0));
                    float u0 = y0 + r;
                    float s0 = (u0 >= 10.0f) ? 1.0f : 0.0f;
                    r = 0.36787944117144233f * (r - 20.0f * s0);

                    // tail step 1 + y1 (y1 = CC1*Znew - tail1) + spike
                    Z2t = DD_H * (Z2t + P2t);
                    P2t = fmaf(DD_H, P2t, xd1);
                    float tail1 = fmaf(CC2_H, P2t, fmaf(CC3_H, Z2t, CC2_L * P2t));
                    float zh = Znew.h + Znew.l;
                    float y1 = fmaf(CC1_H, zh, fmaf(CC1_L, zh, -tail1));
                    float u1 = y1 + r;
                    float s1 = (u1 >= 10.0f) ? 1.0f : 0.0f;
                    r = 0.36787944117144233f * (r - 20.0f * s1);

                    Z = Znew; P = Pnew;
                    sp[h*2+0] = s0; sp[h*2+1] = s1;
                }
                float4 SP = {sp[0], sp[1], sp[2], sp[3]};
                *reinterpret_cast<float4*>(&sx[tid][tq]) = SP;
            }
        }
        __syncthreads();

        if (POOLW == 0) {
            // ---- plain cooperative float4 spike write-out ----
#pragma unroll
            for (int q = 0; q < 8; q++) {
                const int flat = q*128 + tid;
                const int row = flat >> 3, c4 = flat & 7;
                const int nn = n0 + row;
                const int t = t0 + c4*4;
                if (nn < N && t < TT)
                    *reinterpret_cast<float4*>(s + (size_t)nn*TT + t) =
                        *reinterpret_cast<const float4*>(&sx[row][c4*4]);
            }
        } else {
            // ---- fused 2x2 sum-pool: 32 pooled neurons/block, 11*sum exact ----
            constexpr int HALF = POOLW/2;
#pragma unroll
            for (int q = 0; q < 2; q++) {
                const int item = q*128 + tid;
                const int p = item >> 3, c4 = item & 7;
                const int t = t0 + c4*4;
                if (t < TT) {
                    const int hp = p / HALF, wo = p % HALF;
                    const int r00 = 2*hp*POOLW + 2*wo;
                    float4 v00 = *reinterpret_cast<const float4*>(&sx[r00][c4*4]);
                    float4 v01 = *reinterpret_cast<const float4*>(&sx[r00+1][c4*4]);
                    float4 v10 = *reinterpret_cast<const float4*>(&sx[r00+POOLW][c4*4]);
                    float4 v11 = *reinterpret_cast<const float4*>(&sx[r00+POOLW+1][c4*4]);
                    float4 o;
                    o.x = 11.0f * (v00.x + v01.x + v10.x + v11.x);
                    o.y = 11.0f * (v00.y + v01.y + v10.y + v11.y);
                    o.z = 11.0f * (v00.z + v01.z + v10.z + v11.z);
                    o.w = 11.0f * (v00.w + v01.w + v10.w + v11.w);
                    *reinterpret_cast<float4*>(s + (size_t)(n0/4 + p)*TT + t) = o;
                }
            }
        }
        __syncthreads();   // smem reused next tile
    }
}

// =====================================================================
// Dense readout, split-K x4: up[z][b][o][t] = sum_{i in chunk z} s5 * Wf
// s5 binary -> products exact; TwoSum-compensated fp32 chunk sums.
// =====================================================================
__global__ void __launch_bounds__(320)
dense_partial_kernel(const float* __restrict__ s5, const float* __restrict__ wf,
                     float* __restrict__ up)
{
    __shared__ float wrow[1024];
    const int b = blockIdx.x, o = blockIdx.y, z = blockIdx.z;
    const int tid = threadIdx.x;
    for (int i = tid; i < 1024; i += 320) wrow[i] = wf[o*4096 + z*1024 + i];
    __syncthreads();
    if (tid >= TT) return;

    const float* p = s5 + (size_t)b * 4096 * TT + (size_t)z * 1024 * TT;
    float acc = 0.f, comp = 0.f;
    for (int i = 0; i < 1024; i++) {
        const float pr = wrow[i] * p[i*TT + tid];   // exact (x in {0,1})
        float sm = acc + pr;
        float bb = sm - acc;
        comp += (acc - (sm - bb)) + (pr - bb);
        acc = sm;
    }
    up[(size_t)z*48000 + (b*10 + o)*TT + tid] = acc + comp;
}

__global__ void dense_combine_kernel(const float* __restrict__ up, float* __restrict__ u)
{
    const int i = blockIdx.x*256 + threadIdx.x;
    if (i >= 48000) return;
    u[i] = ((up[i] + up[48000 + i]) + up[96000 + i]) + up[144000 + i];
}

// =====================================================================
extern "C" void kernel_launch(void* const* d_in, const int* in_sizes, int n_in,
                              void* d_out, int out_size)
{
    const float *s_in = nullptr, *W1 = nullptr, *W2 = nullptr, *W3 = nullptr, *Wf = nullptr;
    for (int i = 0; i < n_in; i++) {
        switch (in_sizes[i]) {
            case 11097600: s_in = (const float*)d_in[i]; break;   // [16,2,34,34,300]
            case 800:      W1   = (const float*)d_in[i]; break;   // [16,2,5,5]
            case 4608:     W2   = (const float*)d_in[i]; break;   // [32,16,3,3]
            case 18432:    W3   = (const float*)d_in[i]; break;   // [64,32,3,3]
            case 40960:    Wf   = (const float*)d_in[i]; break;   // [10,64,8,8]
        }
    }

    float *a, *sA, *sB, *u, *up;
    cudaGetSymbolAddress((void**)&a,  g_a);
    cudaGetSymbolAddress((void**)&sA, g_sA);
    cudaGetSymbolAddress((void**)&sB, g_sB);
    cudaGetSymbolAddress((void**)&u,  g_u);
    cudaGetSymbolAddress((void**)&up, g_up);

    // L1: conv 5x5 pad1  [16,2,34,34] -> [16,16,32,32]
    conv_kernel<2,2,16,16,5,5,34,34,32,32,1><<<dim3(32,32,16),320>>>(s_in, W1, a);
    // psp+spike+POOL fused: 262144 neurons -> pooled 65536 into sA
    psp_spike_kernel<32><<<2048,128>>>(a, sA, 262144);
    // s2 spikes
    psp_spike_kernel<0><<<512,128>>>(sA, sB, 65536);

    // L3: conv 3x3 pad1 [16,16,16,16] -> [16,32,16,16]  (z = b + 16*co_group)
    conv_kernel<16,8,8,32,3,3,16,16,16,16,1><<<dim3(16,16,64),320>>>(sB, W2, a);
    // psp+spike+POOL fused: 131072 -> pooled 32768 into sA
    psp_spike_kernel<16><<<1024,128>>>(a, sA, 131072);
    // s4 spikes
    psp_spike_kernel<0><<<256,128>>>(sA, sB, 32768);

    // L5: conv 3x3 pad1 [16,32,8,8] -> [16,64,8,8]  (z = b + 16*co_group)
    conv_kernel<32,8,8,64,3,3,8,8,8,8,1><<<dim3(8,8,128),320>>>(sB, W3, a);
    // s5 spikes
    psp_spike_kernel<0><<<512,128>>>(a, sA, 65536);

    // dense readout (split-K x4) + combine + final psp/spike into d_out
    dense_partial_kernel<<<dim3(16,10,4),320>>>(sA, Wf, up);
    dense_combine_kernel<<<188,256>>>(up, u);
    psp_spike_kernel<0><<<2,128>>>(u, (float*)d_out, 160);
}

// round 11
// speedup vs baseline: 1.3145x; 1.3145x over previous
#include <cuda_runtime.h>

#define TT 300

// ---------------- static scratch (no allocations allowed) ----------------
__device__ float g_a [78643200];   // conv outputs (max: layer1, 16*16*32*32*300)
__device__ float g_sA[78643200];   // ping buffer
__device__ float g_sB[19660800];   // pong buffer
__device__ float g_u [48000];      // dense pre-psp output (combined)
__device__ float g_up[192000];     // dense split-K partials (4 x 48000)

// ---------------- double-float constant splits (compile-time folded) ------
constexpr double DDd   = 0.9048374180359595;     // exp(-0.1)
constexpr double D2d   = 0.8187307530779818;     // exp(-0.2)
constexpr double TD2d  = 1.6374615061559637;     // 2*exp(-0.2)
constexpr double CC1d  = 0.2718281828459045;     // e/10
constexpr double CC1Dd = CC1d * DDd;             // (e/10)*exp(-0.1)
constexpr double CC2d  = 1.2340980408667956e-3;  // 10*exp(-9)
constexpr double CC3d  = 1.2340980408667956e-5;  // 0.1*exp(-9)
constexpr float DD_H   = (float)DDd;
constexpr float DD_L   = (float)(DDd   - (double)DD_H);
constexpr float D2_H   = (float)D2d;
constexpr float D2_L   = (float)(D2d   - (double)D2_H);
constexpr float TD2_H  = (float)TD2d;
constexpr float TD2_L  = (float)(TD2d  - (double)TD2_H);
constexpr float CC1_H  = (float)CC1d;
constexpr float CC1_L  = (float)(CC1d  - (double)CC1_H);
constexpr float CC1D_H = (float)CC1Dd;
constexpr float CC1D_L = (float)(CC1Dd - (double)CC1D_H);
constexpr float CC2_H  = (float)CC2d;
constexpr float CC2_L  = (float)(CC2d  - (double)CC2_H);
constexpr float CC3_H  = (float)CC3d;

// ---------------- double-float (two-float) primitives ---------------------
struct df { float h, l; };

__device__ __forceinline__ df df_add(df a, df b) {
    float s  = a.h + b.h;
    float bb = s - a.h;
    float e  = (a.h - (s - bb)) + (b.h - bb);
    e += a.l + b.l;
    float h = s + e;
    float l = e - (h - s);
    return {h, l};
}
__device__ __forceinline__ df df_addf(df a, float b) {
    float s  = a.h + b;
    float bb = s - a.h;
    float e  = (a.h - (s - bb)) + (b - bb);
    e += a.l;
    float h = s + e;
    float l = e - (h - s);
    return {h, l};
}
__device__ __forceinline__ df df_mulc(df a, float ch, float cl) {
    float p = a.h * ch;
    float e = fmaf(a.h, ch, -p);
    e = fmaf(a.h, cl, e);
    e = fmaf(a.l, ch, e);
    float h = p + e;
    float l = e - (h - p);
    return {h, l};
}

// =====================================================================
// Spatial conv, load-minimizing shape: CO_T as LARGE as registers allow so
// each input load amortizes over many FMAs; NL=2 lane-split accumulators
// (combine ~2% overhead). Inputs are binary spikes -> fmaf(w,0,acc) is
// exact, so rounding accrues only on nonzero terms (~rate*chain ~ 10-15):
// error ~1e-6, the regime empirically giving rel_err = 0.
// threads = t (coalesced). z = b + 16*co_group.
// =====================================================================
template<int CI,int NL,int CO_T,int CO_FULL,int KH,int KW,int HIN,int WIN,int HOUT,int WOUT,int PAD>
__global__ void __launch_bounds__(320)
conv_kernel(const float* __restrict__ in, const float* __restrict__ w,
            float* __restrict__ out)
{
    __shared__ __align__(16) float sw[CI*KH*KW*CO_T];
    const int tid = threadIdx.x;
    const int ow = blockIdx.x, oh = blockIdx.y;
    const int b = blockIdx.z & 15;
    const int co_base = (blockIdx.z >> 4) * CO_T;

    for (int i = tid; i < CI*KH*KW*CO_T; i += 320) {
        int k = i / CO_T, co = i % CO_T;
        sw[i] = w[(co_base + co)*(CI*KH*KW) + k];
    }
    __syncthreads();

    const int t = tid;
    if (t >= TT) return;

    float acc[NL][CO_T];
#pragma unroll
    for (int l = 0; l < NL; l++)
#pragma unroll
        for (int c = 0; c < CO_T; c++) acc[l][c] = 0.f;

    for (int g = 0; g < CI/NL; g++) {
#pragma unroll
        for (int l = 0; l < NL; l++) {
            const int ci = g*NL + l;
#pragma unroll
            for (int kh = 0; kh < KH; kh++) {
                const int ih = oh + kh - PAD;
#pragma unroll
                for (int kw = 0; kw < KW; kw++) {
                    const int iw = ow + kw - PAD;
                    const bool valid = ((unsigned)ih < (unsigned)HIN) && ((unsigned)iw < (unsigned)WIN);
                    const float* p = in + ((((b*CI + ci)*HIN + ih)*WIN) + iw)*TT;
                    const float x = valid ? p[t] : 0.f;
                    const float4* wv = reinterpret_cast<const float4*>(&sw[((ci*KH + kh)*KW + kw)*CO_T]);
#pragma unroll
                    for (int c4 = 0; c4 < CO_T/4; c4++) {
                        float4 wq = wv[c4];
                        acc[l][c4*4+0] = fmaf(wq.x, x, acc[l][c4*4+0]);
                        acc[l][c4*4+1] = fmaf(wq.y, x, acc[l][c4*4+1]);
                        acc[l][c4*4+2] = fmaf(wq.z, x, acc[l][c4*4+2]);
                        acc[l][c4*4+3] = fmaf(wq.w, x, acc[l][c4*4+3]);
                    }
                }
            }
        }
    }

    // exact Neumaier combine across lanes (once per output)
#pragma unroll
    for (int c = 0; c < CO_T; c++) {
        float s_  = acc[0][c];
        float cmp = 0.f;
#pragma unroll
        for (int l = 1; l < NL; l++) {
            float bv = acc[l][c];
            float tv = s_ + bv;
            float bb = tv - s_;
            cmp += (s_ - (tv - bb)) + (bv - bb);
            s_ = tv;
        }
        float* q = out + ((((b*CO_FULL) + (co_base + c))*HOUT + oh)*WOUT + ow)*TT;
        q[t] = s_ + cmp;
    }
}

// =====================================================================
// PSP (2-step-blocked double-float IIR + fp32 delayed-tail IIR) fused with
// the bit-exact refractory scan, and (POOLW>0) the SLAYER 2x2 sum-pool
// (11 * sum of 4 binary spikes — exact in fp32, any order).
// POOLW = spatial row width (32 or 16); POOLW=0 -> plain spike output.
// 128 neurons/block; 32-t tiles; float4 staged I/O; next-tile prefetch.
// =====================================================================
template<int POOLW>
__global__ void __launch_bounds__(128)
psp_spike_kernel(const float* __restrict__ a, float* __restrict__ s, int N)
{
    __shared__ __align__(16) float sx[128][36];   // current tile (spikes in-place)
    __shared__ __align__(16) float sd[128][36];   // 100-delayed tile
    const int tid = threadIdx.x;
    const int n0 = blockIdx.x * 128;
    const int n  = n0 + tid;

    df Z = {0.f, 0.f}, P = {0.f, 0.f};
    float Z2t = 0.f, P2t = 0.f;
    float r   = 0.f;

    float4 curv[8], delv[8];

    // ---- prefetch tile 0 ----
#pragma unroll
    for (int q = 0; q < 8; q++) {
        const int flat = q*128 + tid;
        const int row = flat >> 3, c4 = flat & 7;
        const int nn = n0 + row;
        const int t = c4*4;
        float4 v = {0.f,0.f,0.f,0.f}, wv = {0.f,0.f,0.f,0.f};
        if (nn < N && t < TT)
            v = *reinterpret_cast<const float4*>(a + (size_t)nn*TT + t);
        curv[q] = v; delv[q] = wv;
    }

    for (int t0 = 0; t0 < TT; t0 += 32) {
#pragma unroll
        for (int q = 0; q < 8; q++) {
            const int flat = q*128 + tid;
            const int row = flat >> 3, c4 = flat & 7;
            *reinterpret_cast<float4*>(&sx[row][c4*4]) = curv[q];
            *reinterpret_cast<float4*>(&sd[row][c4*4]) = delv[q];
        }
        __syncthreads();

        const int t0n = t0 + 32;
        if (t0n < TT) {
#pragma unroll
            for (int q = 0; q < 8; q++) {
                const int flat = q*128 + tid;
                const int row = flat >> 3, c4 = flat & 7;
                const int nn = n0 + row;
                const int t = t0n + c4*4;
                float4 v = {0.f,0.f,0.f,0.f}, wv = {0.f,0.f,0.f,0.f};
                if (nn < N) {
                    if (t < TT)
                        v = *reinterpret_cast<const float4*>(a + (size_t)nn*TT + t);
                    const int td = t - 100;
                    if (td >= 0 && td < TT)
                        wv = *reinterpret_cast<const float4*>(a + (size_t)nn*TT + td);
                }
                curv[q] = v; delv[q] = wv;
            }
        }

        if (n < N) {
            const int tmax = min(32, TT - t0);    // 32 or 12, both /4
            for (int tq = 0; tq < tmax; tq += 4) {
                float4 X  = *reinterpret_cast<const float4*>(&sx[tid][tq]);
                float4 XD = *reinterpret_cast<const float4*>(&sd[tid][tq]);
                float sp[4];
#pragma unroll
                for (int h = 0; h < 2; h++) {
                    const float x0  = (h == 0) ? X.x  : X.z;
                    const float x1  = (h == 0) ? X.y  : X.w;
                    const float xd0 = (h == 0) ? XD.x : XD.z;
                    const float xd1 = (h == 0) ? XD.y : XD.w;

                    // dx0 = d (x) x0, exact product
                    float ph = DD_H * x0;
                    float pl = fmaf(DD_H, x0, -ph);
                    pl = fmaf(DD_L, x0, pl);
                    // Z_{t+2} = d^2 Z + 2 d^2 P + dx0
                    df A = df_mulc(Z, D2_H, D2_L);
                    df B = df_mulc(P, TD2_H, TD2_L);
                    df Znew = df_add(df_add(A, B), df{ph, pl});
                    // P_{t+2} = d^2 P + dx0 + x1
                    df Cv = df_mulc(P, D2_H, D2_L);
                    df Pnew = df_addf(df_add(Cv, df{ph, pl}), x1);

                    // tail step 0 + y0 (y0 = CC1*d*(Z+P) - tail0) + spike
                    Z2t = DD_H * (Z2t + P2t);
                    P2t = fmaf(DD_H, P2t, xd0);
                    float tail0 = fmaf(CC2_H, P2t, fmaf(CC3_H, Z2t, CC2_L * P2t));
                    float sh = (Z.h + P.h) + (Z.l + P.l);
                    float y0 = fmaf(CC1D_H, sh, fmaf(CC1D_L, sh, -tail0));
                    float u0 = y0 + r;
                    float s0 = (u0 >= 10.0f) ? 1.0f : 0.0f;
                    r = 0.36787944117144233f * (r - 20.0f * s0);

                    // tail step 1 + y1 (y1 = CC1*Znew - tail1) + spike
                    Z2t = DD_H * (Z2t + P2t);
                    P2t = fmaf(DD_H, P2t, xd1);
                    float tail1 = fmaf(CC2_H, P2t, fmaf(CC3_H, Z2t, CC2_L * P2t));
                    float zh = Znew.h + Znew.l;
                    float y1 = fmaf(CC1_H, zh, fmaf(CC1_L, zh, -tail1));
                    float u1 = y1 + r;
                    float s1 = (u1 >= 10.0f) ? 1.0f : 0.0f;
                    r = 0.36787944117144233f * (r - 20.0f * s1);

                    Z = Znew; P = Pnew;
                    sp[h*2+0] = s0; sp[h*2+1] = s1;
                }
                float4 SP = {sp[0], sp[1], sp[2], sp[3]};
                *reinterpret_cast<float4*>(&sx[tid][tq]) = SP;
            }
        }
        __syncthreads();

        if (POOLW == 0) {
            // ---- plain cooperative float4 spike write-out ----
#pragma unroll
            for (int q = 0; q < 8; q++) {
                const int flat = q*128 + tid;
                const int row = flat >> 3, c4 = flat & 7;
                const int nn = n0 + row;
                const int t = t0 + c4*4;
                if (nn < N && t < TT)
                    *reinterpret_cast<float4*>(s + (size_t)nn*TT + t) =
                        *reinterpret_cast<const float4*>(&sx[row][c4*4]);
            }
        } else {
            // ---- fused 2x2 sum-pool: 32 pooled neurons/block, 11*sum exact ----
            constexpr int HALF = POOLW/2;
#pragma unroll
            for (int q = 0; q < 2; q++) {
                const int item = q*128 + tid;
                const int p = item >> 3, c4 = item & 7;
                const int t = t0 + c4*4;
                if (t < TT) {
                    const int hp = p / HALF, wo = p % HALF;
                    const int r00 = 2*hp*POOLW + 2*wo;
                    float4 v00 = *reinterpret_cast<const float4*>(&sx[r00][c4*4]);
                    float4 v01 = *reinterpret_cast<const float4*>(&sx[r00+1][c4*4]);
                    float4 v10 = *reinterpret_cast<const float4*>(&sx[r00+POOLW][c4*4]);
                    float4 v11 = *reinterpret_cast<const float4*>(&sx[r00+POOLW+1][c4*4]);
                    float4 o;
                    o.x = 11.0f * (v00.x + v01.x + v10.x + v11.x);
                    o.y = 11.0f * (v00.y + v01.y + v10.y + v11.y);
                    o.z = 11.0f * (v00.z + v01.z + v10.z + v11.z);
                    o.w = 11.0f * (v00.w + v01.w + v10.w + v11.w);
                    *reinterpret_cast<float4*>(s + (size_t)(n0/4 + p)*TT + t) = o;
                }
            }
        }
        __syncthreads();   // smem reused next tile
    }
}

// =====================================================================
// Dense readout, split-K x4: up[z][b][o][t] = sum_{i in chunk z} s5 * Wf
// s5 binary -> products exact; TwoSum-compensated fp32 chunk sums.
// =====================================================================
__global__ void __launch_bounds__(320)
dense_partial_kernel(const float* __restrict__ s5, const float* __restrict__ wf,
                     float* __restrict__ up)
{
    __shared__ float wrow[1024];
    const int b = blockIdx.x, o = blockIdx.y, z = blockIdx.z;
    const int tid = threadIdx.x;
    for (int i = tid; i < 1024; i += 320) wrow[i] = wf[o*4096 + z*1024 + i];
    __syncthreads();
    if (tid >= TT) return;

    const float* p = s5 + (size_t)b * 4096 * TT + (size_t)z * 1024 * TT;
    float acc = 0.f, comp = 0.f;
    for (int i = 0; i < 1024; i++) {
        const float pr = wrow[i] * p[i*TT + tid];   // exact (x in {0,1})
        float sm = acc + pr;
        float bb = sm - acc;
        comp += (acc - (sm - bb)) + (pr - bb);
        acc = sm;
    }
    up[(size_t)z*48000 + (b*10 + o)*TT + tid] = acc + comp;
}

__global__ void dense_combine_kernel(const float* __restrict__ up, float* __restrict__ u)
{
    const int i = blockIdx.x*256 + threadIdx.x;
    if (i >= 48000) return;
    u[i] = ((up[i] + up[48000 + i]) + up[96000 + i]) + up[144000 + i];
}

// =====================================================================
extern "C" void kernel_launch(void* const* d_in, const int* in_sizes, int n_in,
                              void* d_out, int out_size)
{
    const float *s_in = nullptr, *W1 = nullptr, *W2 = nullptr, *W3 = nullptr, *Wf = nullptr;
    for (int i = 0; i < n_in; i++) {
        switch (in_sizes[i]) {
            case 11097600: s_in = (const float*)d_in[i]; break;   // [16,2,34,34,300]
            case 800:      W1   = (const float*)d_in[i]; break;   // [16,2,5,5]
            case 4608:     W2   = (const float*)d_in[i]; break;   // [32,16,3,3]
            case 18432:    W3   = (const float*)d_in[i]; break;   // [64,32,3,3]
            case 40960:    Wf   = (const float*)d_in[i]; break;   // [10,64,8,8]
        }
    }

    float *a, *sA, *sB, *u, *up;
    cudaGetSymbolAddress((void**)&a,  g_a);
    cudaGetSymbolAddress((void**)&sA, g_sA);
    cudaGetSymbolAddress((void**)&sB, g_sB);
    cudaGetSymbolAddress((void**)&u,  g_u);
    cudaGetSymbolAddress((void**)&up, g_up);

    // L1: conv 5x5 pad1  [16,2,34,34] -> [16,16,32,32]  (CO_T=16, one group)
    conv_kernel<2,2,16,16,5,5,34,34,32,32,1><<<dim3(32,32,16),320>>>(s_in, W1, a);
    // psp+spike+POOL fused: 262144 neurons -> pooled 65536 into sA
    psp_spike_kernel<32><<<2048,128>>>(a, sA, 262144);
    // s2 spikes
    psp_spike_kernel<0><<<512,128>>>(sA, sB, 65536);

    // L3: conv 3x3 pad1 [16,16,16,16] -> [16,32,16,16]  (CO_T=32: ONE group, min loads)
    conv_kernel<16,2,32,32,3,3,16,16,16,16,1><<<dim3(16,16,16),320>>>(sB, W2, a);
    // psp+spike+POOL fused: 131072 -> pooled 32768 into sA
    psp_spike_kernel<16><<<1024,128>>>(a, sA, 131072);
    // s4 spikes
    psp_spike_kernel<0><<<256,128>>>(sA, sB, 32768);

    // L5: conv 3x3 pad1 [16,32,8,8] -> [16,64,8,8]  (CO_T=32: two groups)
    conv_kernel<32,2,32,64,3,3,8,8,8,8,1><<<dim3(8,8,32),320>>>(sB, W3, a);
    // s5 spikes
    psp_spike_kernel<0><<<512,128>>>(a, sA, 65536);

    // dense readout (split-K x4) + combine + final psp/spike into d_out
    dense_partial_kernel<<<dim3(16,10,4),320>>>(sA, Wf, up);
    dense_combine_kernel<<<188,256>>>(up, u);
    psp_spike_kernel<0><<<2,128>>>(u, (float*)d_out, 160);
}

// round 13
// speedup vs baseline: 1.5195x; 1.1559x over previous
#include <cuda_runtime.h>

#define TT 300

// ---------------- static scratch (no allocations allowed) ----------------
__device__ float g_a [78643200];   // conv outputs (max: layer1, 16*16*32*32*300)
__device__ float g_sA[78643200];   // ping buffer
__device__ float g_sB[19660800];   // pong buffer
__device__ float g_u [48000];      // dense pre-psp output (combined)
__device__ float g_up[192000];     // dense split-K partials (4 x 48000)

// ---------------- double-float constant splits (compile-time folded) ------
constexpr double DDd   = 0.9048374180359595;     // exp(-0.1)
constexpr double D2d   = 0.8187307530779818;     // exp(-0.2)
constexpr double TD2d  = 1.6374615061559637;     // 2*exp(-0.2)
constexpr double CC1d  = 0.2718281828459045;     // e/10
constexpr double CC1Dd = CC1d * DDd;             // (e/10)*exp(-0.1)
constexpr double CC2d  = 1.2340980408667956e-3;  // 10*exp(-9)
constexpr double CC3d  = 1.2340980408667956e-5;  // 0.1*exp(-9)
constexpr float DD_H   = (float)DDd;
constexpr float DD_L   = (float)(DDd   - (double)DD_H);
constexpr float D2_H   = (float)D2d;
constexpr float D2_L   = (float)(D2d   - (double)D2_H);
constexpr float TD2_H  = (float)TD2d;
constexpr float TD2_L  = (float)(TD2d  - (double)TD2_H);
constexpr float CC1_H  = (float)CC1d;
constexpr float CC1_L  = (float)(CC1d  - (double)CC1_H);
constexpr float CC1D_H = (float)CC1Dd;
constexpr float CC1D_L = (float)(CC1Dd - (double)CC1D_H);
constexpr float CC2_H  = (float)CC2d;
constexpr float CC2_L  = (float)(CC2d  - (double)CC2_H);
constexpr float CC3_H  = (float)CC3d;

// ---------------- double-float (two-float) primitives ---------------------
struct df { float h, l; };

__device__ __forceinline__ df df_add(df a, df b) {
    float s  = a.h + b.h;
    float bb = s - a.h;
    float e  = (a.h - (s - bb)) + (b.h - bb);
    e += a.l + b.l;
    float h = s + e;
    float l = e - (h - s);
    return {h, l};
}
__device__ __forceinline__ df df_addf(df a, float b) {
    float s  = a.h + b;
    float bb = s - a.h;
    float e  = (a.h - (s - bb)) + (b - bb);
    e += a.l;
    float h = s + e;
    float l = e - (h - s);
    return {h, l};
}
__device__ __forceinline__ df df_mulc(df a, float ch, float cl) {
    float p = a.h * ch;
    float e = fmaf(a.h, ch, -p);
    e = fmaf(a.h, cl, e);
    e = fmaf(a.l, ch, e);
    float h = p + e;
    float l = e - (h - p);
    return {h, l};
}

// =====================================================================
// Spatial conv, load-minimizing shape (CO_T large, NL=2 lane-split accs,
// Neumaier combine ~2%). __launch_bounds__(320,2) forces regs<=102 so TWO
// blocks fit per SM (R10 had 112 regs -> 1 block -> latency-bound at
// occ 15%, issue 45%). Loads batched per ci-group into a prefetch array
// to raise MLP. Binary-spike inputs keep fp32 chain error ~1e-6.
// threads = t (coalesced). z = b + 16*co_group.
// =====================================================================
template<int CI,int NL,int CO_T,int CO_FULL,int KH,int KW,int HIN,int WIN,int HOUT,int WOUT,int PAD>
__global__ void __launch_bounds__(320, 2)
conv_kernel(const float* __restrict__ in, const float* __restrict__ w,
            float* __restrict__ out)
{
    __shared__ __align__(16) float sw[CI*KH*KW*CO_T];
    const int tid = threadIdx.x;
    const int ow = blockIdx.x, oh = blockIdx.y;
    const int b = blockIdx.z & 15;
    const int co_base = (blockIdx.z >> 4) * CO_T;

    for (int i = tid; i < CI*KH*KW*CO_T; i += 320) {
        int k = i / CO_T, co = i % CO_T;
        sw[i] = w[(co_base + co)*(CI*KH*KW) + k];
    }
    __syncthreads();

    const int t = tid;
    if (t >= TT) return;

    float acc[NL][CO_T];
#pragma unroll
    for (int l = 0; l < NL; l++)
#pragma unroll
        for (int c = 0; c < CO_T; c++) acc[l][c] = 0.f;

    for (int g = 0; g < CI/NL; g++) {
        // ---- batched load phase: all NL*KH*KW inputs for this group ----
        float xv[NL][KH*KW];
#pragma unroll
        for (int l = 0; l < NL; l++) {
            const int ci = g*NL + l;
#pragma unroll
            for (int kh = 0; kh < KH; kh++) {
                const int ih = oh + kh - PAD;
#pragma unroll
                for (int kw = 0; kw < KW; kw++) {
                    const int iw = ow + kw - PAD;
                    const bool valid = ((unsigned)ih < (unsigned)HIN) && ((unsigned)iw < (unsigned)WIN);
                    const float* p = in + ((((b*CI + ci)*HIN + ih)*WIN) + iw)*TT;
                    xv[l][kh*KW + kw] = valid ? p[t] : 0.f;
                }
            }
        }
        // ---- FMA burst ----
#pragma unroll
        for (int l = 0; l < NL; l++) {
            const int ci = g*NL + l;
#pragma unroll
            for (int k = 0; k < KH*KW; k++) {
                const float x = xv[l][k];
                const float4* wv = reinterpret_cast<const float4*>(&sw[(ci*KH*KW + k)*CO_T]);
#pragma unroll
                for (int c4 = 0; c4 < CO_T/4; c4++) {
                    float4 wq = wv[c4];
                    acc[l][c4*4+0] = fmaf(wq.x, x, acc[l][c4*4+0]);
                    acc[l][c4*4+1] = fmaf(wq.y, x, acc[l][c4*4+1]);
                    acc[l][c4*4+2] = fmaf(wq.z, x, acc[l][c4*4+2]);
                    acc[l][c4*4+3] = fmaf(wq.w, x, acc[l][c4*4+3]);
                }
            }
        }
    }

    // exact Neumaier combine across lanes (once per output)
#pragma unroll
    for (int c = 0; c < CO_T; c++) {
        float s_  = acc[0][c];
        float cmp = 0.f;
#pragma unroll
        for (int l = 1; l < NL; l++) {
            float bv = acc[l][c];
            float tv = s_ + bv;
            float bb = tv - s_;
            cmp += (s_ - (tv - bb)) + (bv - bb);
            s_ = tv;
        }
        float* q = out + ((((b*CO_FULL) + (co_base + c))*HOUT + oh)*WOUT + ow)*TT;
        q[t] = s_ + cmp;
    }
}

// =====================================================================
// PSP (2-step-blocked double-float IIR + fp32 delayed-tail IIR) fused with
// the bit-exact refractory scan, and (POOLW>0) the SLAYER 2x2 sum-pool
// (11 * sum of 4 binary spikes — exact in fp32, any order).
// POOLW = spatial row width (32 or 16); POOLW=0 -> plain spike output.
// 128 neurons/block; 32-t tiles; float4 staged I/O; next-tile prefetch.
// =====================================================================
template<int POOLW>
__global__ void __launch_bounds__(128)
psp_spike_kernel(const float* __restrict__ a, float* __restrict__ s, int N)
{
    __shared__ __align__(16) float sx[128][36];   // current tile (spikes in-place)
    __shared__ __align__(16) float sd[128][36];   // 100-delayed tile
    const int tid = threadIdx.x;
    const int n0 = blockIdx.x * 128;
    const int n  = n0 + tid;

    df Z = {0.f, 0.f}, P = {0.f, 0.f};
    float Z2t = 0.f, P2t = 0.f;
    float r   = 0.f;

    float4 curv[8], delv[8];

    // ---- prefetch tile 0 ----
#pragma unroll
    for (int q = 0; q < 8; q++) {
        const int flat = q*128 + tid;
        const int row = flat >> 3, c4 = flat & 7;
        const int nn = n0 + row;
        const int t = c4*4;
        float4 v = {0.f,0.f,0.f,0.f}, wv = {0.f,0.f,0.f,0.f};
        if (nn < N && t < TT)
            v = *reinterpret_cast<const float4*>(a + (size_t)nn*TT + t);
        curv[q] = v; delv[q] = wv;
    }

    for (int t0 = 0; t0 < TT; t0 += 32) {
#pragma unroll
        for (int q = 0; q < 8; q++) {
            const int flat = q*128 + tid;
            const int row = flat >> 3, c4 = flat & 7;
            *reinterpret_cast<float4*>(&sx[row][c4*4]) = curv[q];
            *reinterpret_cast<float4*>(&sd[row][c4*4]) = delv[q];
        }
        __syncthreads();

        const int t0n = t0 + 32;
        if (t0n < TT) {
#pragma unroll
            for (int q = 0; q < 8; q++) {
                const int flat = q*128 + tid;
                const int row = flat >> 3, c4 = flat & 7;
                const int nn = n0 + row;
                const int t = t0n + c4*4;
                float4 v = {0.f,0.f,0.f,0.f}, wv = {0.f,0.f,0.f,0.f};
                if (nn < N) {
                    if (t < TT)
                        v = *reinterpret_cast<const float4*>(a + (size_t)nn*TT + t);
                    const int td = t - 100;
                    if (td >= 0 && td < TT)
                        wv = *reinterpret_cast<const float4*>(a + (size_t)nn*TT + td);
                }
                curv[q] = v; delv[q] = wv;
            }
        }

        if (n < N) {
            const int tmax = min(32, TT - t0);    // 32 or 12, both /4
            for (int tq = 0; tq < tmax; tq += 4) {
                float4 X  = *reinterpret_cast<const float4*>(&sx[tid][tq]);
                float4 XD = *reinterpret_cast<const float4*>(&sd[tid][tq]);
                float sp[4];
#pragma unroll
                for (int h = 0; h < 2; h++) {
                    const float x0  = (h == 0) ? X.x  : X.z;
                    const float x1  = (h == 0) ? X.y  : X.w;
                    const float xd0 = (h == 0) ? XD.x : XD.z;
                    const float xd1 = (h == 0) ? XD.y : XD.w;

                    // dx0 = d (x) x0, exact product
                    float ph = DD_H * x0;
                    float pl = fmaf(DD_H, x0, -ph);
                    pl = fmaf(DD_L, x0, pl);
                    // Z_{t+2} = d^2 Z + 2 d^2 P + dx0
                    df A = df_mulc(Z, D2_H, D2_L);
                    df B = df_mulc(P, TD2_H, TD2_L);
                    df Znew = df_add(df_add(A, B), df{ph, pl});
                    // P_{t+2} = d^2 P + dx0 + x1
                    df Cv = df_mulc(P, D2_H, D2_L);
                    df Pnew = df_addf(df_add(Cv, df{ph, pl}), x1);

                    // tail step 0 + y0 (y0 = CC1*d*(Z+P) - tail0) + spike
                    Z2t = DD_H * (Z2t + P2t);
                    P2t = fmaf(DD_H, P2t, xd0);
                    float tail0 = fmaf(CC2_H, P2t, fmaf(CC3_H, Z2t, CC2_L * P2t));
                    float sh = (Z.h + P.h) + (Z.l + P.l);
                    float y0 = fmaf(CC1D_H, sh, fmaf(CC1D_L, sh, -tail0));
                    float u0 = y0 + r;
                    float s0 = (u0 >= 10.0f) ? 1.0f : 0.0f;
                    r = 0.36787944117144233f * (r - 20.0f * s0);

                    // tail step 1 + y1 (y1 = CC1*Znew - tail1) + spike
                    Z2t = DD_H * (Z2t + P2t);
                    P2t = fmaf(DD_H, P2t, xd1);
                    float tail1 = fmaf(CC2_H, P2t, fmaf(CC3_H, Z2t, CC2_L * P2t));
                    float zh = Znew.h + Znew.l;
                    float y1 = fmaf(CC1_H, zh, fmaf(CC1_L, zh, -tail1));
                    float u1 = y1 + r;
                    float s1 = (u1 >= 10.0f) ? 1.0f : 0.0f;
                    r = 0.36787944117144233f * (r - 20.0f * s1);

                    Z = Znew; P = Pnew;
                    sp[h*2+0] = s0; sp[h*2+1] = s1;
                }
                float4 SP = {sp[0], sp[1], sp[2], sp[3]};
                *reinterpret_cast<float4*>(&sx[tid][tq]) = SP;
            }
        }
        __syncthreads();

        if (POOLW == 0) {
            // ---- plain cooperative float4 spike write-out ----
#pragma unroll
            for (int q = 0; q < 8; q++) {
                const int flat = q*128 + tid;
                const int row = flat >> 3, c4 = flat & 7;
                const int nn = n0 + row;
                const int t = t0 + c4*4;
                if (nn < N && t < TT)
                    *reinterpret_cast<float4*>(s + (size_t)nn*TT + t) =
                        *reinterpret_cast<const float4*>(&sx[row][c4*4]);
            }
        } else {
            // ---- fused 2x2 sum-pool: 32 pooled neurons/block, 11*sum exact ----
            constexpr int HALF = POOLW/2;
#pragma unroll
            for (int q = 0; q < 2; q++) {
                const int item = q*128 + tid;
                const int p = item >> 3, c4 = item & 7;
                const int t = t0 + c4*4;
                if (t < TT) {
                    const int hp = p / HALF, wo = p % HALF;
                    const int r00 = 2*hp*POOLW + 2*wo;
                    float4 v00 = *reinterpret_cast<const float4*>(&sx[r00][c4*4]);
                    float4 v01 = *reinterpret_cast<const float4*>(&sx[r00+1][c4*4]);
                    float4 v10 = *reinterpret_cast<const float4*>(&sx[r00+POOLW][c4*4]);
                    float4 v11 = *reinterpret_cast<const float4*>(&sx[r00+POOLW+1][c4*4]);
                    float4 o;
                    o.x = 11.0f * (v00.x + v01.x + v10.x + v11.x);
                    o.y = 11.0f * (v00.y + v01.y + v10.y + v11.y);
                    o.z = 11.0f * (v00.z + v01.z + v10.z + v11.z);
                    o.w = 11.0f * (v00.w + v01.w + v10.w + v11.w);
                    *reinterpret_cast<float4*>(s + (size_t)(n0/4 + p)*TT + t) = o;
                }
            }
        }
        __syncthreads();   // smem reused next tile
    }
}

// =====================================================================
// Dense readout, split-K x4: up[z][b][o][t] = sum_{i in chunk z} s5 * Wf
// s5 binary -> products exact; TwoSum-compensated fp32 chunk sums.
// =====================================================================
__global__ void __launch_bounds__(320)
dense_partial_kernel(const float* __restrict__ s5, const float* __restrict__ wf,
                     float* __restrict__ up)
{
    __shared__ float wrow[1024];
    const int b = blockIdx.x, o = blockIdx.y, z = blockIdx.z;
    const int tid = threadIdx.x;
    for (int i = tid; i < 1024; i += 320) wrow[i] = wf[o*4096 + z*1024 + i];
    __syncthreads();
    if (tid >= TT) return;

    const float* p = s5 + (size_t)b * 4096 * TT + (size_t)z * 1024 * TT;
    float acc = 0.f, comp = 0.f;
    for (int i = 0; i < 1024; i++) {
        const float pr = wrow[i] * p[i*TT + tid];   // exact (x in {0,1})
        float sm = acc + pr;
        float bb = sm - acc;
        comp += (acc - (sm - bb)) + (pr - bb);
        acc = sm;
    }
    up[(size_t)z*48000 + (b*10 + o)*TT + tid] = acc + comp;
}

__global__ void dense_combine_kernel(const float* __restrict__ up, float* __restrict__ u)
{
    const int i = blockIdx.x*256 + threadIdx.x;
    if (i >= 48000) return;
    u[i] = ((up[i] + up[48000 + i]) + up[96000 + i]) + up[144000 + i];
}

// =====================================================================
extern "C" void kernel_launch(void* const* d_in, const int* in_sizes, int n_in,
                              void* d_out, int out_size)
{
    const float *s_in = nullptr, *W1 = nullptr, *W2 = nullptr, *W3 = nullptr, *Wf = nullptr;
    for (int i = 0; i < n_in; i++) {
        switch (in_sizes[i]) {
            case 11097600: s_in = (const float*)d_in[i]; break;   // [16,2,34,34,300]
            case 800:      W1   = (const float*)d_in[i]; break;   // [16,2,5,5]
            case 4608:     W2   = (const float*)d_in[i]; break;   // [32,16,3,3]
            case 18432:    W3   = (const float*)d_in[i]; break;   // [64,32,3,3]
            case 40960:    Wf   = (const float*)d_in[i]; break;   // [10,64,8,8]
        }
    }

    float *a, *sA, *sB, *u, *up;
    cudaGetSymbolAddress((void**)&a,  g_a);
    cudaGetSymbolAddress((void**)&sA, g_sA);
    cudaGetSymbolAddress((void**)&sB, g_sB);
    cudaGetSymbolAddress((void**)&u,  g_u);
    cudaGetSymbolAddress((void**)&up, g_up);

    // L1: conv 5x5 pad1  [16,2,34,34] -> [16,16,32,32]  (CO_T=16, one group)
    conv_kernel<2,2,16,16,5,5,34,34,32,32,1><<<dim3(32,32,16),320>>>(s_in, W1, a);
    // psp+spike+POOL fused: 262144 neurons -> pooled 65536 into sA
    psp_spike_kernel<32><<<2048,128>>>(a, sA, 262144);
    // s2 spikes
    psp_spike_kernel<0><<<512,128>>>(sA, sB, 65536);

    // L3: conv 3x3 pad1 [16,16,16,16] -> [16,32,16,16]  (CO_T=32: ONE group, min loads)
    conv_kernel<16,2,32,32,3,3,16,16,16,16,1><<<dim3(16,16,16),320>>>(sB, W2, a);
    // psp+spike+POOL fused: 131072 -> pooled 32768 into sA
    psp_spike_kernel<16><<<1024,128>>>(a, sA, 131072);
    // s4 spikes
    psp_spike_kernel<0><<<256,128>>>(sA, sB, 32768);

    // L5: conv 3x3 pad1 [16,32,8,8] -> [16,64,8,8]  (CO_T=32: two groups)
    conv_kernel<32,2,32,64,3,3,8,8,8,8,1><<<dim3(8,8,32),320>>>(sB, W3, a);
    // s5 spikes
    psp_spike_kernel<0><<<512,128>>>(a, sA, 65536);

    // dense readout (split-K x4) + combine + final psp/spike into d_out
    dense_partial_kernel<<<dim3(16,10,4),320>>>(sA, Wf, up);
    dense_combine_kernel<<<188,256>>>(up, u);
    psp_spike_kernel<0><<<2,128>>>(u, (float*)d_out, 160);
}